// round 13
// baseline (speedup 1.0000x reference)
#include <cuda_runtime.h>
#include <cstdint>

// Problem constants (fixed by the reference).
#define N_KEYS   65536
#define EMB      1024
#define KSEL     512
#define BATCH    128
#define NBINS    65536   // top 16 bits of ordered float (256 KB hist).
                         // Evidence: 4096 bins -> ~5us atomic serialization in
                         // sim (R11 48.8us vs R3 43.6us); 65536 bins + NO
                         // in-kernel tail is the proven-fast config (R3).
#define CAND_CAP 2048    // candidate capacity (expected ~540 used)

// -------- scratch (no allocations allowed: __device__ globals) --------
// Zero-initialized at module load. Re-arm protocol per invocation:
//   g_hist  : zeroed by add_kernel blocks 0..63 (distributed, after all
//             hist readers in K2 have finished — stream order).
//   g_ccnt/g_done2 : reset by K2's elected last block.
__device__ float              g_sims[N_KEYS];
__device__ unsigned int       g_hist[NBINS];
__device__ unsigned long long g_cand[CAND_CAP];
__device__ unsigned int       g_ccnt;
__device__ int                g_topk[KSEL];
__device__ unsigned int       g_done2;

// Monotone float -> uint transform: a > b  <=>  ford(a) > ford(b)
__device__ __forceinline__ unsigned int ford(float f) {
    unsigned int u = __float_as_uint(f);
    return (u & 0x80000000u) ? ~u : (u | 0x80000000u);
}

// ---------------------------------------------------------------------
// K1: PURE sims + histogram (DRAM-bound). No tail, no election, no fence
// — byte-identical structure to R3's 43.6us @ 78.9% DRAM kernel.
// One warp per key row, 8 warps/block, grid = 8192.
// ---------------------------------------------------------------------
__global__ void __launch_bounds__(256)
sim_kernel(const float* __restrict__ keys,
           const float* __restrict__ query) {
    const int warp = threadIdx.x >> 5;
    const int lane = threadIdx.x & 31;
    const int n    = blockIdx.x * 8 + warp;

    const float4* k4 = reinterpret_cast<const float4*>(keys) + (size_t)n * (EMB / 4);
    const float4* q4 = reinterpret_cast<const float4*>(query);

    float dot = 0.f, sq = 0.f;
#pragma unroll
    for (int l = 0; l < 8; ++l) {
        float4 kv = k4[lane + 32 * l];
        float4 qv = __ldg(&q4[lane + 32 * l]);
        dot = fmaf(kv.x, qv.x, dot);
        dot = fmaf(kv.y, qv.y, dot);
        dot = fmaf(kv.z, qv.z, dot);
        dot = fmaf(kv.w, qv.w, dot);
        sq  = fmaf(kv.x, kv.x, sq);
        sq  = fmaf(kv.y, kv.y, sq);
        sq  = fmaf(kv.z, kv.z, sq);
        sq  = fmaf(kv.w, kv.w, sq);
    }
#pragma unroll
    for (int o = 16; o > 0; o >>= 1) {
        dot += __shfl_xor_sync(0xFFFFFFFFu, dot, o);
        sq  += __shfl_xor_sync(0xFFFFFFFFu, sq,  o);
    }
    if (lane == 0) {
        float nrm = __fsqrt_rn(fmaxf(sq, 1e-16f));   // max(norm, 1e-8)
        float sim = __fdiv_rn(dot, nrm);             // q-norm scale omitted (order-invariant)
        g_sims[n] = sim;
        atomicAdd(&g_hist[ford(sim) >> 16], 1u);     // 64K bins: ~1 hit/bin
    }
}

// ---------------------------------------------------------------------
// K2: 16 blocks x 1024 threads.
//  Phase A (every block, redundantly, in parallel): rank-512 threshold
//    from the 256 KB histogram via two-level suffix scan (64 bins/thread,
//    then a 64-thread scan of the winning chunk). L2-broadcast reads.
//  Phase B: each block compacts its 1/16 slice of g_sims vs T
//    (~540 global atomics total).
//  Phase C (last block): exact O(n^2) rank placement of candidates.
//    key = (ord<<32)|~idx => rank order == jax top_k (desc val, asc idx).
// ---------------------------------------------------------------------
__global__ void __launch_bounds__(1024)
compact_rank_kernel() {
    const int t = threadIdx.x;

    // ---- Phase A: threshold (redundant per block) ----
    __shared__ int          s_sum[1024];   // level-1 chunk suffix sums
    __shared__ int          s_bins[64];    // level-2: winning chunk's bins
    __shared__ int          s_tstar, s_bstar;

    {   // thread t sums bins [64t, 64t+64): 16x uint4
        const uint4* h4 = reinterpret_cast<const uint4*>(g_hist) + t * 16;
        unsigned int s = 0;
#pragma unroll
        for (int i = 0; i < 16; ++i) { uint4 v = h4[i]; s += v.x + v.y + v.z + v.w; }
        s_sum[t] = (int)s;
    }
    __syncthreads();

    // Hillis-Steele suffix scan: s_sum[t] = count of sims in bins >= 64t
    for (int d = 1; d < 1024; d <<= 1) {
        int v = s_sum[t] + ((t + d < 1024) ? s_sum[t + d] : 0);
        __syncthreads();
        s_sum[t] = v;
        __syncthreads();
    }

    if (s_sum[t] >= KSEL && (t == 1023 || s_sum[t + 1] < KSEL)) s_tstar = t;
    __syncthreads();
    const int tstar = s_tstar;
    const int above = (tstar < 1023) ? s_sum[tstar + 1] : 0;  // count above chunk

    // level 2: suffix scan the winning chunk's 64 bins
    if (t < 64) s_bins[t] = (int)g_hist[tstar * 64 + t];
    __syncthreads();
    for (int d = 1; d < 64; d <<= 1) {
        int v = 0;
        if (t < 64) v = s_bins[t] + ((t + d < 64) ? s_bins[t + d] : 0);
        __syncthreads();
        if (t < 64) s_bins[t] = v;
        __syncthreads();
    }
    if (t < 64 && above + s_bins[t] >= KSEL &&
        (t == 63 || above + s_bins[t + 1] < KSEL)) s_bstar = t;
    __syncthreads();
    const unsigned int T = ((unsigned int)(tstar * 64 + s_bstar)) << 16;

    // ---- Phase B: compact this block's slice ----
    {
        const int i4 = blockIdx.x * 1024 + t;    // 0..16383 (float4 index)
        float4 v = reinterpret_cast<const float4*>(g_sims)[i4];
        unsigned int u0 = ford(v.x), u1 = ford(v.y), u2 = ford(v.z), u3 = ford(v.w);
        int base = i4 * 4;
        if (u0 >= T) { unsigned int p = atomicAdd(&g_ccnt, 1u); if (p < CAND_CAP)
            g_cand[p] = ((unsigned long long)u0 << 32) | (unsigned int)~(unsigned int)(base + 0); }
        if (u1 >= T) { unsigned int p = atomicAdd(&g_ccnt, 1u); if (p < CAND_CAP)
            g_cand[p] = ((unsigned long long)u1 << 32) | (unsigned int)~(unsigned int)(base + 1); }
        if (u2 >= T) { unsigned int p = atomicAdd(&g_ccnt, 1u); if (p < CAND_CAP)
            g_cand[p] = ((unsigned long long)u2 << 32) | (unsigned int)~(unsigned int)(base + 2); }
        if (u3 >= T) { unsigned int p = atomicAdd(&g_ccnt, 1u); if (p < CAND_CAP)
            g_cand[p] = ((unsigned long long)u3 << 32) | (unsigned int)~(unsigned int)(base + 3); }
    }

    // ---- last-block election ----
    __shared__ unsigned int s_is_last;
    __syncthreads();
    if (t == 0) {
        __threadfence();
        s_is_last = (atomicAdd(&g_done2, 1u) == gridDim.x - 1) ? 1u : 0u;
    }
    __syncthreads();
    if (!s_is_last) return;
    __threadfence();

    // ---- Phase C: exact ranking of ~540 candidates ----
    __shared__ unsigned long long s_key[CAND_CAP];
    const unsigned int ccnt = g_ccnt;
    const int cnt = (ccnt < CAND_CAP) ? (int)ccnt : CAND_CAP;

    for (int i = t; i < cnt; i += 1024) s_key[i] = g_cand[i];
    __syncthreads();

    for (int i = t; i < cnt; i += 1024) {
        const unsigned long long ki = s_key[i];
        int rank = 0;
        for (int j = 0; j < cnt; ++j)            // broadcast smem reads
            rank += (s_key[j] > ki);
        if (rank < KSEL)
            g_topk[rank] = (int)(~(unsigned int)(ki & 0xFFFFFFFFull));
    }

    // ---- re-arm counters (hist re-zero is done by add_kernel, spread) ----
    __syncthreads();
    if (t == 0) { g_ccnt = 0u; g_done2 = 0u; }
}

// ---------------------------------------------------------------------
// K3: out[b,k,:] = x[b,k,:] + prompts[topk[k], :]
// One block per (b,k) row; thread t handles float4 t of the row.
// x/out streamed (cs hints measured faster here: 83.3 -> 80.4us) so the
// 512 selected prompt rows (2 MB) stay L2-resident across all batches.
// Blocks 0..63 additionally zero the 256 KB histogram (4 KB each) for the
// next invocation — distributed, effectively free, and safely ordered
// after K2's hist reads by stream order.
// ---------------------------------------------------------------------
__global__ void __launch_bounds__(256)
add_kernel(const float4* __restrict__ x,
           const float4* __restrict__ prompts,
           float4* __restrict__ out) {
    const int bid = blockIdx.x;            // b*512 + k
    const int k   = bid & (KSEL - 1);
    const int t   = threadIdx.x;           // 0..255
    const int row = g_topk[k];

    if (bid < 64)                          // 64 blocks * 256 thr * 16B = 256 KB
        reinterpret_cast<uint4*>(g_hist)[bid * 256 + t] = make_uint4(0u, 0u, 0u, 0u);

    const size_t xo = (size_t)bid * (EMB / 4) + t;
    float4 xv = __ldcs(&x[xo]);                          // streaming read-once
    float4 pv = __ldg(&prompts[(size_t)row * (EMB / 4) + t]);
    xv.x += pv.x; xv.y += pv.y; xv.z += pv.z; xv.w += pv.w;
    __stcs(&out[xo], xv);                                // streaming write-once
}

// ---------------------------------------------------------------------
extern "C" void kernel_launch(void* const* d_in, const int* in_sizes, int n_in,
                              void* d_out, int out_size) {
    const float* x       = (const float*)d_in[0];   // [128, 512, 1024]
    const float* query   = (const float*)d_in[1];   // [1024]
    const float* keys    = (const float*)d_in[2];   // [65536, 1024]
    const float* prompts = (const float*)d_in[3];   // [65536, 1024]
    float* out           = (float*)d_out;           // [128, 512, 1024]

    sim_kernel<<<N_KEYS / 8, 256>>>(keys, query);
    compact_rank_kernel<<<16, 1024>>>();
    add_kernel<<<BATCH * KSEL, 256>>>(reinterpret_cast<const float4*>(x),
                                      reinterpret_cast<const float4*>(prompts),
                                      reinterpret_cast<float4*>(out));
}

// round 14
// speedup vs baseline: 1.0377x; 1.0377x over previous
#include <cuda_runtime.h>
#include <cstdint>

// Problem constants (fixed by the reference).
#define N_KEYS   65536
#define EMB      1024
#define KSEL     512
#define BATCH    128
#define NBINS    65536   // top 16 bits of ordered float (256 KB hist).
                         // 64K bins: ~1 hit/bin -> no atomic serialization in
                         // sim (proven 42.2us @ 81.7% DRAM in R13).
#define CAND_CAP 2048    // candidate capacity (expected ~540 used)

// -------- scratch (no allocations allowed: __device__ globals) --------
// Zero-initialized at module load. Re-arm protocol per invocation:
//   g_hist  : zeroed by add_kernel blocks 0..63 (distributed+coalesced,
//             ordered after K2's hist reads by stream order).
//   g_ccnt/g_done2 : reset by K2's elected last block.
__device__ float              g_sims[N_KEYS];
__device__ unsigned int       g_hist[NBINS];
__device__ unsigned long long g_cand[CAND_CAP];
__device__ unsigned int       g_ccnt;
__device__ int                g_topk[KSEL];
__device__ unsigned int       g_done2;

// Monotone float -> uint transform: a > b  <=>  ford(a) > ford(b)
__device__ __forceinline__ unsigned int ford(float f) {
    unsigned int u = __float_as_uint(f);
    return (u & 0x80000000u) ? ~u : (u | 0x80000000u);
}

// ---------------------------------------------------------------------
// K1: PURE sims + histogram (DRAM-bound). No tail, no election, no fence.
// One warp per key row, 8 warps/block, grid = 8192.  (42.2us @ 81.7%)
// ---------------------------------------------------------------------
__global__ void __launch_bounds__(256)
sim_kernel(const float* __restrict__ keys,
           const float* __restrict__ query) {
    const int warp = threadIdx.x >> 5;
    const int lane = threadIdx.x & 31;
    const int n    = blockIdx.x * 8 + warp;

    const float4* k4 = reinterpret_cast<const float4*>(keys) + (size_t)n * (EMB / 4);
    const float4* q4 = reinterpret_cast<const float4*>(query);

    float dot = 0.f, sq = 0.f;
#pragma unroll
    for (int l = 0; l < 8; ++l) {
        float4 kv = k4[lane + 32 * l];
        float4 qv = __ldg(&q4[lane + 32 * l]);
        dot = fmaf(kv.x, qv.x, dot);
        dot = fmaf(kv.y, qv.y, dot);
        dot = fmaf(kv.z, qv.z, dot);
        dot = fmaf(kv.w, qv.w, dot);
        sq  = fmaf(kv.x, kv.x, sq);
        sq  = fmaf(kv.y, kv.y, sq);
        sq  = fmaf(kv.z, kv.z, sq);
        sq  = fmaf(kv.w, kv.w, sq);
    }
#pragma unroll
    for (int o = 16; o > 0; o >>= 1) {
        dot += __shfl_xor_sync(0xFFFFFFFFu, dot, o);
        sq  += __shfl_xor_sync(0xFFFFFFFFu, sq,  o);
    }
    if (lane == 0) {
        float nrm = __fsqrt_rn(fmaxf(sq, 1e-16f));   // max(norm, 1e-8)
        float sim = __fdiv_rn(dot, nrm);             // q-norm scale omitted (order-invariant)
        g_sims[n] = sim;
        atomicAdd(&g_hist[ford(sim) >> 16], 1u);     // 64K bins: ~1 hit/bin
    }
}

// ---------------------------------------------------------------------
// K2: 16 blocks x 1024 threads.
//  Phase A (every block, redundantly, in parallel): rank-512 threshold
//    from the 256 KB histogram. R14 FIX: COALESCED reads — iteration i,
//    thread t loads uint4 (i*1024 + t) (lane-consecutive), then a 16-lane
//    shfl segment-reduction forms each 64-bin chunk sum. Was: 256 B/thread
//    consecutive => 32 lines per LDG.128 => ~16k wavefronts/block (~9us).
//  Phase B: each block compacts its 1/16 slice of g_sims vs T.
//  Phase C (last block): exact O(n^2) rank placement of candidates.
//    key = (ord<<32)|~idx => rank order == jax top_k (desc val, asc idx).
// ---------------------------------------------------------------------
__global__ void __launch_bounds__(1024)
compact_rank_kernel() {
    const int t    = threadIdx.x;
    const int lane = t & 31;

    // ---- Phase A: threshold (redundant per block, coalesced) ----
    __shared__ int s_chunk[1024];   // chunk c = bins [64c, 64c+64)
    __shared__ int s_bins[64];      // winning chunk's bins (suffix sums)
    __shared__ int s_tstar, s_bstar;

#pragma unroll
    for (int i = 0; i < 16; ++i) {
        const int j = i * 1024 + t;                       // uint4 index, coalesced
        uint4 v = reinterpret_cast<const uint4*>(g_hist)[j];
        int s = (int)(v.x + v.y + v.z + v.w);
        // 16-lane segment reduction: lanes {0,16} end with their segment's sum
#pragma unroll
        for (int o = 8; o > 0; o >>= 1)
            s += __shfl_down_sync(0xFFFFFFFFu, s, o, 16);
        if ((lane & 15) == 0)
            s_chunk[j >> 4] = s;                          // 16 uint4s per chunk
    }
    __syncthreads();

    // Hillis-Steele suffix scan: s_chunk[c] = count of sims in bins >= 64c
    for (int d = 1; d < 1024; d <<= 1) {
        int v = s_chunk[t] + ((t + d < 1024) ? s_chunk[t + d] : 0);
        __syncthreads();
        s_chunk[t] = v;
        __syncthreads();
    }

    if (s_chunk[t] >= KSEL && (t == 1023 || s_chunk[t + 1] < KSEL)) s_tstar = t;
    __syncthreads();
    const int tstar = s_tstar;
    const int above = (tstar < 1023) ? s_chunk[tstar + 1] : 0;  // count above chunk

    // level 2: suffix scan the winning chunk's 64 bins (coalesced 64 reads)
    if (t < 64) s_bins[t] = (int)g_hist[tstar * 64 + t];
    __syncthreads();
    for (int d = 1; d < 64; d <<= 1) {
        int v = 0;
        if (t < 64) v = s_bins[t] + ((t + d < 64) ? s_bins[t + d] : 0);
        __syncthreads();
        if (t < 64) s_bins[t] = v;
        __syncthreads();
    }
    if (t < 64 && above + s_bins[t] >= KSEL &&
        (t == 63 || above + s_bins[t + 1] < KSEL)) s_bstar = t;
    __syncthreads();
    const unsigned int T = ((unsigned int)(tstar * 64 + s_bstar)) << 16;

    // ---- Phase B: compact this block's slice (coalesced) ----
    {
        const int i4 = blockIdx.x * 1024 + t;    // 0..16383 (float4 index)
        float4 v = reinterpret_cast<const float4*>(g_sims)[i4];
        unsigned int u0 = ford(v.x), u1 = ford(v.y), u2 = ford(v.z), u3 = ford(v.w);
        int base = i4 * 4;
        if (u0 >= T) { unsigned int p = atomicAdd(&g_ccnt, 1u); if (p < CAND_CAP)
            g_cand[p] = ((unsigned long long)u0 << 32) | (unsigned int)~(unsigned int)(base + 0); }
        if (u1 >= T) { unsigned int p = atomicAdd(&g_ccnt, 1u); if (p < CAND_CAP)
            g_cand[p] = ((unsigned long long)u1 << 32) | (unsigned int)~(unsigned int)(base + 1); }
        if (u2 >= T) { unsigned int p = atomicAdd(&g_ccnt, 1u); if (p < CAND_CAP)
            g_cand[p] = ((unsigned long long)u2 << 32) | (unsigned int)~(unsigned int)(base + 2); }
        if (u3 >= T) { unsigned int p = atomicAdd(&g_ccnt, 1u); if (p < CAND_CAP)
            g_cand[p] = ((unsigned long long)u3 << 32) | (unsigned int)~(unsigned int)(base + 3); }
    }

    // ---- last-block election ----
    __shared__ unsigned int s_is_last;
    __syncthreads();
    if (t == 0) {
        __threadfence();
        s_is_last = (atomicAdd(&g_done2, 1u) == gridDim.x - 1) ? 1u : 0u;
    }
    __syncthreads();
    if (!s_is_last) return;
    __threadfence();

    // ---- Phase C: exact ranking of ~540 candidates ----
    __shared__ unsigned long long s_key[CAND_CAP];
    const unsigned int ccnt = g_ccnt;
    const int cnt = (ccnt < CAND_CAP) ? (int)ccnt : CAND_CAP;

    for (int i = t; i < cnt; i += 1024) s_key[i] = g_cand[i];
    __syncthreads();

    for (int i = t; i < cnt; i += 1024) {
        const unsigned long long ki = s_key[i];
        int rank = 0;
        for (int j = 0; j < cnt; ++j)            // broadcast smem reads
            rank += (s_key[j] > ki);
        if (rank < KSEL)
            g_topk[rank] = (int)(~(unsigned int)(ki & 0xFFFFFFFFull));
    }

    // ---- re-arm counters (hist re-zero is done by add_kernel, spread) ----
    __syncthreads();
    if (t == 0) { g_ccnt = 0u; g_done2 = 0u; }
}

// ---------------------------------------------------------------------
// K3: out[b,k,:] = x[b,k,:] + prompts[topk[k], :]
// One block per (b,k) row; thread t handles float4 t of the row.
// x/out streamed (cs hints measured faster here: 83.3 -> 80.4us) so the
// 512 selected prompt rows (2 MB) stay L2-resident across all batches.
// Blocks 0..63 additionally zero the 256 KB histogram (coalesced 4 KB
// each) for the next invocation — ordered after K2 by stream order.
// ---------------------------------------------------------------------
__global__ void __launch_bounds__(256)
add_kernel(const float4* __restrict__ x,
           const float4* __restrict__ prompts,
           float4* __restrict__ out) {
    const int bid = blockIdx.x;            // b*512 + k
    const int k   = bid & (KSEL - 1);
    const int t   = threadIdx.x;           // 0..255
    const int row = g_topk[k];

    if (bid < 64)                          // 64 blocks * 256 thr * 16B = 256 KB
        reinterpret_cast<uint4*>(g_hist)[bid * 256 + t] = make_uint4(0u, 0u, 0u, 0u);

    const size_t xo = (size_t)bid * (EMB / 4) + t;
    float4 xv = __ldcs(&x[xo]);                          // streaming read-once
    float4 pv = __ldg(&prompts[(size_t)row * (EMB / 4) + t]);
    xv.x += pv.x; xv.y += pv.y; xv.z += pv.z; xv.w += pv.w;
    __stcs(&out[xo], xv);                                // streaming write-once
}

// ---------------------------------------------------------------------
extern "C" void kernel_launch(void* const* d_in, const int* in_sizes, int n_in,
                              void* d_out, int out_size) {
    const float* x       = (const float*)d_in[0];   // [128, 512, 1024]
    const float* query   = (const float*)d_in[1];   // [1024]
    const float* keys    = (const float*)d_in[2];   // [65536, 1024]
    const float* prompts = (const float*)d_in[3];   // [65536, 1024]
    float* out           = (float*)d_out;           // [128, 512, 1024]

    sim_kernel<<<N_KEYS / 8, 256>>>(keys, query);
    compact_rank_kernel<<<16, 1024>>>();
    add_kernel<<<BATCH * KSEL, 256>>>(reinterpret_cast<const float4*>(x),
                                      reinterpret_cast<const float4*>(prompts),
                                      reinterpret_cast<float4*>(out));
}

// round 15
// speedup vs baseline: 1.0502x; 1.0121x over previous
#include <cuda_runtime.h>
#include <cstdint>

// Problem constants (fixed by the reference).
#define N_KEYS   65536
#define EMB      1024
#define KSEL     512
#define BATCH    128
#define NBINS    65536   // top 16 bits of ordered float (256 KB hist).
                         // 64K bins: ~1 hit/bin -> no atomic serialization in
                         // sim (proven 42.2us @ 81.7% DRAM in R13/R14).
#define CAND_CAP 2048    // candidate capacity (expected ~540 used)
#define GRID2    16      // K2 grid size (all co-resident -> grid barrier safe)

// -------- scratch (no allocations allowed: __device__ globals) --------
// Zero-initialized at module load. Re-arm protocol per invocation:
//   g_hist  : zeroed by add_kernel blocks 0..63 (distributed+coalesced,
//             ordered after K2's hist reads by stream order).
//   g_ccnt/g_done2/g_bar : reset by K2's elected last block.
__device__ float              g_sims[N_KEYS];
__device__ unsigned int       g_hist[NBINS];
__device__ int                g_chunk[1024];     // 64-bin chunk sums
__device__ unsigned long long g_cand[CAND_CAP];
__device__ unsigned int       g_ccnt;
__device__ int                g_topk[KSEL];
__device__ unsigned int       g_done2, g_bar;

// Monotone float -> uint transform: a > b  <=>  ford(a) > ford(b)
__device__ __forceinline__ unsigned int ford(float f) {
    unsigned int u = __float_as_uint(f);
    return (u & 0x80000000u) ? ~u : (u | 0x80000000u);
}

// ---------------------------------------------------------------------
// K1: PURE sims + histogram (DRAM-bound). No tail, no election, no fence.
// One warp per key row, 8 warps/block, grid = 8192.  (42.3us @ 81.4%)
// ---------------------------------------------------------------------
__global__ void __launch_bounds__(256)
sim_kernel(const float* __restrict__ keys,
           const float* __restrict__ query) {
    const int warp = threadIdx.x >> 5;
    const int lane = threadIdx.x & 31;
    const int n    = blockIdx.x * 8 + warp;

    const float4* k4 = reinterpret_cast<const float4*>(keys) + (size_t)n * (EMB / 4);
    const float4* q4 = reinterpret_cast<const float4*>(query);

    float dot = 0.f, sq = 0.f;
#pragma unroll
    for (int l = 0; l < 8; ++l) {
        float4 kv = k4[lane + 32 * l];
        float4 qv = __ldg(&q4[lane + 32 * l]);
        dot = fmaf(kv.x, qv.x, dot);
        dot = fmaf(kv.y, qv.y, dot);
        dot = fmaf(kv.z, qv.z, dot);
        dot = fmaf(kv.w, qv.w, dot);
        sq  = fmaf(kv.x, kv.x, sq);
        sq  = fmaf(kv.y, kv.y, sq);
        sq  = fmaf(kv.z, kv.z, sq);
        sq  = fmaf(kv.w, kv.w, sq);
    }
#pragma unroll
    for (int o = 16; o > 0; o >>= 1) {
        dot += __shfl_xor_sync(0xFFFFFFFFu, dot, o);
        sq  += __shfl_xor_sync(0xFFFFFFFFu, sq,  o);
    }
    if (lane == 0) {
        float nrm = __fsqrt_rn(fmaxf(sq, 1e-16f));   // max(norm, 1e-8)
        float sim = __fdiv_rn(dot, nrm);             // q-norm scale omitted (order-invariant)
        g_sims[n] = sim;
        atomicAdd(&g_hist[ford(sim) >> 16], 1u);     // 64K bins: ~1 hit/bin
    }
}

// ---------------------------------------------------------------------
// K2: 16 blocks x 1024 threads, with a manual grid barrier (16 blocks
// are trivially all co-resident on 148 SMs -> spin-wait is safe).
//  Phase A1: each block reduces ITS OWN 16 KB hist slice (one coalesced
//    uint4/thread + 16-lane shfl segment-reduce) -> g_chunk[64b..64b+63].
//    Hist is read exactly ONCE grid-wide (R14 read it 16x redundantly
//    from DRAM: ~8-10us).
//  [grid barrier]
//  Phase A2 (redundant, cheap): scan the 4 KB g_chunk -> tstar; read the
//    winning chunk's 64 bins -> threshold T.
//  Phase B: each block compacts its 1/16 slice of g_sims vs T.
//  Phase C (elected last block): exact O(n^2) rank placement.
//    key = (ord<<32)|~idx => rank order == jax top_k (desc val, asc idx).
// ---------------------------------------------------------------------
__global__ void __launch_bounds__(1024)
compact_rank_kernel() {
    const int t    = threadIdx.x;
    const int lane = t & 31;
    const int b    = blockIdx.x;

    // ---- Phase A1: reduce own hist slice to 64 chunk sums ----
    {
        const int j = b * 1024 + t;                       // uint4 index, coalesced
        uint4 v = reinterpret_cast<const uint4*>(g_hist)[j];
        int s = (int)(v.x + v.y + v.z + v.w);
#pragma unroll
        for (int o = 8; o > 0; o >>= 1)                   // 16-lane segment reduce
            s += __shfl_down_sync(0xFFFFFFFFu, s, o, 16);
        if ((lane & 15) == 0)
            g_chunk[64 * b + (t >> 4)] = s;               // chunk = 64 bins
    }

    // ---- grid barrier (release -> arrive -> spin -> acquire) ----
    __syncthreads();
    if (t == 0) {
        __threadfence();                                  // release g_chunk writes
        atomicAdd(&g_bar, 1u);
        while (*((volatile unsigned int*)&g_bar) < GRID2) { }
    }
    __syncthreads();
    __threadfence();                                      // acquire

    // ---- Phase A2: threshold from g_chunk (4 KB, L2-hot, redundant) ----
    __shared__ int s_chunk[1024];
    __shared__ int s_bins[64];
    __shared__ int s_tstar, s_bstar;

    s_chunk[t] = g_chunk[t];                              // coalesced
    __syncthreads();

    // Hillis-Steele suffix scan: s_chunk[c] = count of sims in bins >= 64c
    for (int d = 1; d < 1024; d <<= 1) {
        int v = s_chunk[t] + ((t + d < 1024) ? s_chunk[t + d] : 0);
        __syncthreads();
        s_chunk[t] = v;
        __syncthreads();
    }

    if (s_chunk[t] >= KSEL && (t == 1023 || s_chunk[t + 1] < KSEL)) s_tstar = t;
    __syncthreads();
    const int tstar = s_tstar;
    const int above = (tstar < 1023) ? s_chunk[tstar + 1] : 0;  // count above chunk

    // level 2: suffix scan the winning chunk's 64 bins
    if (t < 64) s_bins[t] = (int)g_hist[tstar * 64 + t];
    __syncthreads();
    for (int d = 1; d < 64; d <<= 1) {
        int v = 0;
        if (t < 64) v = s_bins[t] + ((t + d < 64) ? s_bins[t + d] : 0);
        __syncthreads();
        if (t < 64) s_bins[t] = v;
        __syncthreads();
    }
    if (t < 64 && above + s_bins[t] >= KSEL &&
        (t == 63 || above + s_bins[t + 1] < KSEL)) s_bstar = t;
    __syncthreads();
    const unsigned int T = ((unsigned int)(tstar * 64 + s_bstar)) << 16;

    // ---- Phase B: compact this block's slice (coalesced) ----
    {
        const int i4 = b * 1024 + t;             // 0..16383 (float4 index)
        float4 v = reinterpret_cast<const float4*>(g_sims)[i4];
        unsigned int u0 = ford(v.x), u1 = ford(v.y), u2 = ford(v.z), u3 = ford(v.w);
        int base = i4 * 4;
        if (u0 >= T) { unsigned int p = atomicAdd(&g_ccnt, 1u); if (p < CAND_CAP)
            g_cand[p] = ((unsigned long long)u0 << 32) | (unsigned int)~(unsigned int)(base + 0); }
        if (u1 >= T) { unsigned int p = atomicAdd(&g_ccnt, 1u); if (p < CAND_CAP)
            g_cand[p] = ((unsigned long long)u1 << 32) | (unsigned int)~(unsigned int)(base + 1); }
        if (u2 >= T) { unsigned int p = atomicAdd(&g_ccnt, 1u); if (p < CAND_CAP)
            g_cand[p] = ((unsigned long long)u2 << 32) | (unsigned int)~(unsigned int)(base + 2); }
        if (u3 >= T) { unsigned int p = atomicAdd(&g_ccnt, 1u); if (p < CAND_CAP)
            g_cand[p] = ((unsigned long long)u3 << 32) | (unsigned int)~(unsigned int)(base + 3); }
    }

    // ---- last-block election ----
    __shared__ unsigned int s_is_last;
    __syncthreads();
    if (t == 0) {
        __threadfence();
        s_is_last = (atomicAdd(&g_done2, 1u) == gridDim.x - 1) ? 1u : 0u;
    }
    __syncthreads();
    if (!s_is_last) return;
    __threadfence();

    // ---- Phase C: exact ranking of ~540 candidates ----
    __shared__ unsigned long long s_key[CAND_CAP];
    const unsigned int ccnt = g_ccnt;
    const int cnt = (ccnt < CAND_CAP) ? (int)ccnt : CAND_CAP;

    for (int i = t; i < cnt; i += 1024) s_key[i] = g_cand[i];
    __syncthreads();

    for (int i = t; i < cnt; i += 1024) {
        const unsigned long long ki = s_key[i];
        int rank = 0;
        for (int j = 0; j < cnt; ++j)            // broadcast smem reads
            rank += (s_key[j] > ki);
        if (rank < KSEL)
            g_topk[rank] = (int)(~(unsigned int)(ki & 0xFFFFFFFFull));
    }

    // ---- re-arm counters (hist re-zero is done by add_kernel, spread) ----
    __syncthreads();
    if (t == 0) { g_ccnt = 0u; g_done2 = 0u; g_bar = 0u; }
}

// ---------------------------------------------------------------------
// K3: out[b,k,:] = x[b,k,:] + prompts[topk[k], :]
// One block per (b,k) row; thread t handles float4 t of the row.
// x/out streamed (cs hints measured faster here: 83.3 -> 80.4us) so the
// 512 selected prompt rows (2 MB) stay L2-resident across all batches.
// Blocks 0..63 additionally zero the 256 KB histogram (coalesced 4 KB
// each) for the next invocation — ordered after K2 by stream order.
// ---------------------------------------------------------------------
__global__ void __launch_bounds__(256)
add_kernel(const float4* __restrict__ x,
           const float4* __restrict__ prompts,
           float4* __restrict__ out) {
    const int bid = blockIdx.x;            // b*512 + k
    const int k   = bid & (KSEL - 1);
    const int t   = threadIdx.x;           // 0..255
    const int row = g_topk[k];

    if (bid < 64)                          // 64 blocks * 256 thr * 16B = 256 KB
        reinterpret_cast<uint4*>(g_hist)[bid * 256 + t] = make_uint4(0u, 0u, 0u, 0u);

    const size_t xo = (size_t)bid * (EMB / 4) + t;
    float4 xv = __ldcs(&x[xo]);                          // streaming read-once
    float4 pv = __ldg(&prompts[(size_t)row * (EMB / 4) + t]);
    xv.x += pv.x; xv.y += pv.y; xv.z += pv.z; xv.w += pv.w;
    __stcs(&out[xo], xv);                                // streaming write-once
}

// ---------------------------------------------------------------------
extern "C" void kernel_launch(void* const* d_in, const int* in_sizes, int n_in,
                              void* d_out, int out_size) {
    const float* x       = (const float*)d_in[0];   // [128, 512, 1024]
    const float* query   = (const float*)d_in[1];   // [1024]
    const float* keys    = (const float*)d_in[2];   // [65536, 1024]
    const float* prompts = (const float*)d_in[3];   // [65536, 1024]
    float* out           = (float*)d_out;           // [128, 512, 1024]

    sim_kernel<<<N_KEYS / 8, 256>>>(keys, query);
    compact_rank_kernel<<<GRID2, 1024>>>();
    add_kernel<<<BATCH * KSEL, 256>>>(reinterpret_cast<const float4*>(x),
                                      reinterpret_cast<const float4*>(prompts),
                                      reinterpret_cast<float4*>(out));
}